// round 4
// baseline (speedup 1.0000x reference)
#include <cuda_runtime.h>
#include <cstdint>

// Scratch (no allocations allowed): per-block partials + completion ticket.
#define MAX_BLOCKS 2048
__device__ float g_partials[MAX_BLOCKS];
__device__ unsigned int g_ticket = 0;   // always 0 between calls (last block resets)

__device__ __forceinline__ float edge_pair_term(const float4* __restrict__ X,
                                                int4 e, float2 w) {
    float4 a0 = __ldg(&X[e.x]);
    float4 b0 = __ldg(&X[e.y]);
    float4 a1 = __ldg(&X[e.z]);
    float4 b1 = __ldg(&X[e.w]);
    float dx0 = a0.x - b0.x, dy0 = a0.y - b0.y, dz0 = a0.z - b0.z, dw0 = a0.w - b0.w;
    float dx1 = a1.x - b1.x, dy1 = a1.y - b1.y, dz1 = a1.z - b1.z, dw1 = a1.w - b1.w;
    float d20 = dx0 * dx0 + dy0 * dy0 + dz0 * dz0 + dw0 * dw0;
    float d21 = dx1 * dx1 + dy1 * dy1 + dz1 * dz1 + dw1 * dw1;
    return fmaf(w.x, d20, w.y * d21);
}

// Single fused kernel, 2x software-pipelined grid-stride main loop:
// 4 edges (8 independent float4 gathers) in flight per thread per iteration.
__global__ void __launch_bounds__(256)
mde_fused_kernel(const float4* __restrict__ X,
                 const int4* __restrict__ epairs,   // 2 edges per element
                 const float2* __restrict__ wpairs, // 2 weights per element
                 int npairs,
                 const int2* __restrict__ etail,    // leftover single edge view
                 const float* __restrict__ wtail,
                 int p,                             // total edges
                 float* __restrict__ out,
                 float inv_p) {
    float acc = 0.0f;
    int stride = gridDim.x * blockDim.x;
    int tid = blockIdx.x * blockDim.x + threadIdx.x;

    int k = tid;
    // Unrolled-by-2 main loop: issue both edge-pair loads + all 8 gathers
    // before consuming, so the scoreboard holds 8 outstanding gathers.
    for (; k + stride < npairs; k += 2 * stride) {
        int4   eA = __ldcs(&epairs[k]);
        int4   eB = __ldcs(&epairs[k + stride]);
        float2 wA = __ldcs(&wpairs[k]);
        float2 wB = __ldcs(&wpairs[k + stride]);
        float tA = edge_pair_term(X, eA, wA);
        float tB = edge_pair_term(X, eB, wB);
        acc += tA + tB;
    }
    for (; k < npairs; k += stride) {
        int4   e = __ldcs(&epairs[k]);
        float2 w = __ldcs(&wpairs[k]);
        acc += edge_pair_term(X, e, w);
    }

    // Tail edges (p odd).
    int tail_base = npairs * 2;
    for (int t = tail_base + tid; t < p; t += stride) {
        int2 e = __ldg(&etail[t]);
        float4 a = __ldg(&X[e.x]);
        float4 b = __ldg(&X[e.y]);
        float dx = a.x - b.x, dy = a.y - b.y, dz = a.z - b.z, dw = a.w - b.w;
        acc = fmaf(__ldg(&wtail[t]), dx * dx + dy * dy + dz * dz + dw * dw, acc);
    }

    // Warp reduction
    #pragma unroll
    for (int off = 16; off > 0; off >>= 1)
        acc += __shfl_down_sync(0xffffffffu, acc, off);

    __shared__ float warp_sums[8];
    int lane = threadIdx.x & 31;
    int wid  = threadIdx.x >> 5;
    if (lane == 0) warp_sums[wid] = acc;
    __syncthreads();

    __shared__ bool is_last;
    if (wid == 0) {
        float v = (lane < 8) ? warp_sums[lane] : 0.0f;
        #pragma unroll
        for (int off = 4; off > 0; off >>= 1)
            v += __shfl_down_sync(0xffffffffu, v, off);
        if (lane == 0) {
            g_partials[blockIdx.x] = v;
            __threadfence();
            unsigned int done = atomicInc(&g_ticket, gridDim.x - 1);
            is_last = (done == gridDim.x - 1);  // wraps to 0 on last -> ticket reset
        }
    }
    __syncthreads();

    // Last block reduces the per-block partials and writes the mean.
    if (is_last) {
        double s = 0.0;
        for (int i = threadIdx.x; i < gridDim.x; i += blockDim.x)
            s += (double)g_partials[i];
        __shared__ double dsums[8];
        #pragma unroll
        for (int off = 16; off > 0; off >>= 1)
            s += __shfl_down_sync(0xffffffffu, s, off);
        if (lane == 0) dsums[wid] = s;
        __syncthreads();
        if (wid == 0) {
            double t = (lane < 8) ? dsums[lane] : 0.0;
            #pragma unroll
            for (int off = 4; off > 0; off >>= 1)
                t += __shfl_down_sync(0xffffffffu, t, off);
            if (lane == 0)
                out[0] = (float)(t * (double)inv_p);
        }
    }
}

extern "C" void kernel_launch(void* const* d_in, const int* in_sizes, int n_in,
                              void* d_out, int out_size) {
    // Inputs: X (f32, 1M x 4), edges (int32, 10M x 2), weights (f32, 10M)
    const float4* X     = (const float4*)d_in[0];
    const int*    edges = (const int*)d_in[1];
    const float*  w     = (const float*)d_in[2];
    float*        out   = (float*)d_out;

    int p = in_sizes[2];
    int npairs = p / 2;

    const int threads = 256;
    int blocks = 1184;  // 148 SMs * 8 blocks -> 2048 threads/SM
    if (blocks > MAX_BLOCKS) blocks = MAX_BLOCKS;

    mde_fused_kernel<<<blocks, threads>>>(
        X,
        (const int4*)edges, (const float2*)w, npairs,
        (const int2*)edges, w, p,
        out, 1.0f / (float)p);
}